// round 12
// baseline (speedup 1.0000x reference)
#include <cuda_runtime.h>

#define Nn   2048      // B*S
#define Bv   16
#define Sv   128
#define Hv   256
#define DINv 256
#define DEv  192
#define DRv  64
#define Ev   2032      // B*(S-1)
#define Lv   12
#define NCTA 128       // 16 trees x 8 column groups (16 clusters of 8)
#define NTHR 512
#define NMBAR 24
#define MBAR_OFF 198656          // byte offset of mbarrier region in smem
#define SMEM_BYTES (198656 + 192)

// packed fp32x2 FMA (sm_103a FFMA2)
#define FFMA2(acc, a, b) asm("fma.rn.f32x2 %0, %1, %2, %0;" : "+l"(acc) : "l"(a), "l"(b))

__device__ __forceinline__ float pairsum(unsigned long long v) {
    float lo, hi;
    asm("mov.b64 {%0, %1}, %2;" : "=f"(lo), "=f"(hi) : "l"(v));
    return lo + hi;
}

__device__ __forceinline__ unsigned smem_u32(const void* p) {
    unsigned a;
    asm("{ .reg .u64 t; cvta.to.shared.u64 t, %1; cvt.u32.u64 %0, t; }"
        : "=r"(a) : "l"(p));
    return a;
}

// mbarrier helpers (cluster scope; no per-level CCTL/L1 flush)
#define MBAR_INIT(addr, count) \
    asm volatile("mbarrier.init.shared.b64 [%0], %1;" :: "r"(addr), "r"(count) : "memory")
__device__ __forceinline__ void mbar_arrive_peer(unsigned mbar, unsigned rank) {
    asm volatile(
        "{ .reg .b32 ra;\n"
        "  mapa.shared::cluster.u32 ra, %0, %1;\n"
        "  mbarrier.arrive.shared::cluster.b64 _, [ra]; }"
        :: "r"(mbar), "r"(rank) : "memory");
}
__device__ __forceinline__ void mbar_wait0(unsigned mbar) {
    asm volatile(
        "{ .reg .pred P;\n"
        "W%=: mbarrier.try_wait.parity.acquire.cluster.shared::cta.b64 P, [%0], 0, 0x989680;\n"
        "  @!P bra W%=; }"
        :: "r"(mbar) : "memory");
}

// ---------------- device scratch (no allocations allowed) ----------------
__device__ float g_proj[4][Nn * Hv];   // i(+bi+bih), f(+bf+bfh), o, u  (column-local)
__device__ float g_h[Nn * Hv];
__device__ float g_c[Nn * Hv];         // column-local
__device__ float g_fh[Nn * Hv];        // W_fh . h  (column-local)
__device__ float g_pooled[Bv * Hv];
__device__ int   g_coff[Nn + 1];
__device__ int   g_children[Ev];
__device__ int   g_tl_off[512];        // [16][32] per-tree level offsets
__device__ int   g_tl_nodes[Nn];
__device__ int   g_tmax[Bv];
__device__ unsigned g_pdone[Bv * 32];

// fence-free release/acquire primitives (for the final head gather)
__device__ __forceinline__ unsigned ld_acq(unsigned* p) {
    unsigned v;
    asm volatile("ld.acquire.gpu.global.u32 %0, [%1];" : "=r"(v) : "l"(p) : "memory");
    return v;
}
__device__ __forceinline__ void red_add_rel(unsigned* p, unsigned v) {
    asm volatile("red.release.gpu.global.add.u32 [%0], %1;" :: "l"(p), "r"(v) : "memory");
}

__device__ __forceinline__ float sigf(float x) {
    return 1.0f / (1.0f + __expf(-x));
}

// ---------------- setup: CSR + per-tree level buckets ---------------------
__global__ void setup_kernel(const int* __restrict__ child_idx,
                             const int* __restrict__ parent_idx,
                             const int* __restrict__ node_height) {
    __shared__ int cnt[Nn];
    __shared__ int psm[Ev];
    __shared__ int hsm[Nn];
    __shared__ int part[256];
    __shared__ int lvl[512];
    __shared__ int lfill[512];
    __shared__ int loff[512];
    const int tid = threadIdx.x;               // 1024 threads
    for (int i = tid; i < Nn; i += 1024) { cnt[i] = 0; hsm[i] = node_height[i]; }
    for (int i = tid; i < Ev; i += 1024) psm[i] = parent_idx[i];
    for (int i = tid; i < 512; i += 1024) { lvl[i] = 0; lfill[i] = 0; }
    if (tid < Bv) g_pdone[tid * 32] = 0u;
    __syncthreads();
    for (int e = tid; e < Ev; e += 1024) atomicAdd(&cnt[psm[e]], 1);
    for (int n = tid; n < Nn; n += 1024) atomicAdd(&lvl[(n >> 7) * 32 + hsm[n]], 1);
    __syncthreads();
    if (tid < 256) { int s = 0; for (int i = 0; i < 8; i++) s += cnt[tid * 8 + i]; part[tid] = s; }
    __syncthreads();
    if (tid == 0) {
        int run = 0;
        for (int i = 0; i < 256; i++) { int v = part[i]; part[i] = run; run += v; }
    }
    if (tid < 16) {                            // per-tree level prefix + maxlev
        int run = 0, mx = 1;
        for (int l = 0; l < 32; l++) {
            loff[tid * 32 + l] = tid * 128 + run;
            if (lvl[tid * 32 + l] > 0) mx = l;
            run += lvl[tid * 32 + l];
        }
        g_tmax[tid] = mx;
    }
    __syncthreads();
    for (int i = tid; i < 512; i += 1024) g_tl_off[i] = loff[i];
    if (tid < 256) {
        int run = part[tid];
        for (int i = 0; i < 8; i++) { int idx = tid * 8 + i; g_coff[idx] = run; run += cnt[idx]; }
        if (tid == 255) g_coff[Nn] = run;
    }
    __syncthreads();
    // deterministic CSR scatter: rank = #earlier same-parent edges (same batch)
    for (int e = tid; e < Ev; e += 1024) {
        int p = psm[e];
        int bstart = (e / (Sv - 1)) * (Sv - 1);
        int rank = 0;
        for (int e2 = bstart; e2 < e; e2++) rank += (psm[e2] == p);
        g_children[g_coff[p] + rank] = child_idx[e];
    }
    // per-tree level bucket fill (intra-level order numerically irrelevant)
    for (int n = tid; n < Nn; n += 1024) {
        int key = (n >> 7) * 32 + hsm[n];
        int r = atomicAdd(&lfill[key], 1);
        g_tl_nodes[loff[key] + r] = n;
    }
}

// ---------------- persistent kernel: cluster/tree, mbar level signaling ---
__global__ void __launch_bounds__(NTHR, 1) __cluster_dims__(8, 1, 1)
main_kernel(const int* __restrict__ xs, const int* __restrict__ rels,
            const int* __restrict__ nheight,
            const float* __restrict__ emb_W, const float* __restrict__ rel_W,
            const float* __restrict__ W_ix, const float* __restrict__ b_ix,
            const float* __restrict__ W_ih, const float* __restrict__ b_ih,
            const float* __restrict__ W_fx, const float* __restrict__ b_fx,
            const float* __restrict__ W_fh, const float* __restrict__ b_fh,
            const float* __restrict__ W_ox, const float* __restrict__ W_oh,
            const float* __restrict__ W_ux, const float* __restrict__ W_uh,
            const float* __restrict__ W_out, const float* __restrict__ b_out,
            float* __restrict__ out) {
    extern __shared__ float sm[];
    float* Wi4 = sm;                  // col-slice layout [(k>>2)*128 + col*4 + (k&3)]
    float* Wo4 = sm + 8192;
    float* Wu4 = sm + 16384;
    float* Wf4 = sm + 24576;
    float* scratch = sm + 32768;      // 16384 floats = 16 warps x 1024
    int*   meta = (int*)(sm + 49152); // 512 ints
    int* sm_tloff = meta;             // 33
    int* sm_tln   = meta + 33;        // 128 node ids (global)
    int* sm_coff  = meta + 161;       // 129, rebased
    int* sm_child = meta + 290;       // <=127 child node ids (global)

    const int tid  = threadIdx.x;
    const int lane = tid & 31;
    const int warp = tid >> 5;
    const int blk  = blockIdx.x;
    const int b    = blk >> 3;        // tree id (cluster id)
    const int g    = blk & 7;         // column group (cluster rank)
    const int J    = g * 32 + lane;
    float* xw = scratch + warp * 1024; // 4 nodes x 256 staging
    const unsigned mbar_base = smem_u32((const char*)sm + MBAR_OFF);

    // ---- phase 0: weights (input-side) + tree metadata + mbar init -------
    {
        const int jb2 = g * 32;
        for (int it = 0; it < 16; it++) {
            int k = it * 16 + (tid >> 5);
            int col = tid & 31;
            int didx = (k >> 2) * 128 + col * 4 + (k & 3);
            int sidx = k * Hv + jb2 + col;
            Wi4[didx] = W_ix[sidx];
            Wo4[didx] = W_ox[sidx];
            Wu4[didx] = W_ux[sidx];
            Wf4[didx] = W_fx[sidx];
        }
        if (tid < 32) sm_tloff[tid] = g_tl_off[b * 32 + tid] - b * 128;
        if (tid >= 32 && tid < 160) sm_tln[tid - 32] = g_tl_nodes[b * 128 + (tid - 32)];
        int cbase = g_coff[b * 128];
        int cend  = g_coff[b * 128 + 128];
        if (tid >= 160 && tid < 289) sm_coff[tid - 160] = g_coff[b * 128 + (tid - 160)] - cbase;
        for (int i = tid; i < cend - cbase; i += NTHR) sm_child[i] = g_children[cbase + i];
        if (tid == 0) {
            for (int l = 0; l < NMBAR; l++) MBAR_INIT(mbar_base + l * 8, 8);
        }
    }
    const float bi = b_ix[J] + b_ih[J];
    const float bf = b_fx[J] + b_fh[J];
    __syncthreads();
    // one-time cluster barrier: peers' mbarriers must be initialized before
    // any remote arrive (the only CCTL/L1-flush point in the kernel)
    asm volatile("barrier.cluster.arrive.aligned;" ::: "memory");
    asm volatile("barrier.cluster.wait.aligned;" ::: "memory");

    // ---- P1: 4 projections, 4 nodes/warp-iter; leaves finished inline ----
    {
        for (int t = 0; t < 2; t++) {
            int nb = b * Sv + (warp + t * 16) * 4;   // 4 contiguous nodes
            int hgt0 = nheight[nb + 0], hgt1 = nheight[nb + 1];
            int hgt2 = nheight[nb + 2], hgt3 = nheight[nb + 3];
            __syncwarp();
            #pragma unroll
            for (int mm = 0; mm < 4; mm++) {
                int n = nb + mm;
                const float4* er = (const float4*)(emb_W + (size_t)xs[n] * DEv);
                const float4* rr = (const float4*)(rel_W + (size_t)rels[n] * DRv);
                float4 a = er[lane];
                float4 bb = (lane < 16) ? er[lane + 32] : rr[lane - 16];
                float4* dm = (float4*)(xw + mm * 256);
                dm[lane] = a; dm[lane + 32] = bb;
            }
            __syncwarp();
            unsigned long long acc[16];
            #pragma unroll
            for (int q = 0; q < 16; q++) acc[q] = 0ull;
            #pragma unroll 4
            for (int k4 = 0; k4 < 64; k4++) {
                ulonglong2 wi = *(const ulonglong2*)&Wi4[k4 * 128 + lane * 4];
                ulonglong2 wf = *(const ulonglong2*)&Wf4[k4 * 128 + lane * 4];
                ulonglong2 wo = *(const ulonglong2*)&Wo4[k4 * 128 + lane * 4];
                ulonglong2 wu = *(const ulonglong2*)&Wu4[k4 * 128 + lane * 4];
                #pragma unroll
                for (int mm = 0; mm < 4; mm++) {
                    ulonglong2 xv = *(const ulonglong2*)&xw[mm * 256 + k4 * 4];
                    FFMA2(acc[mm * 4 + 0], xv.x, wi.x); FFMA2(acc[mm * 4 + 0], xv.y, wi.y);
                    FFMA2(acc[mm * 4 + 1], xv.x, wf.x); FFMA2(acc[mm * 4 + 1], xv.y, wf.y);
                    FFMA2(acc[mm * 4 + 2], xv.x, wo.x); FFMA2(acc[mm * 4 + 2], xv.y, wo.y);
                    FFMA2(acc[mm * 4 + 3], xv.x, wu.x); FFMA2(acc[mm * 4 + 3], xv.y, wu.y);
                }
            }
            #pragma unroll
            for (int mm = 0; mm < 4; mm++) {
                int hgt = (mm == 0) ? hgt0 : (mm == 1) ? hgt1 : (mm == 2) ? hgt2 : hgt3;
                size_t nx = (size_t)(nb + mm) * Hv + J;
                float vi = pairsum(acc[mm * 4 + 0]) + bi;
                float vf = pairsum(acc[mm * 4 + 1]) + bf;
                float vo = pairsum(acc[mm * 4 + 2]);
                float vu = pairsum(acc[mm * 4 + 3]);
                if (hgt == 0) {
                    // leaf: finish the whole cell now (no proj stores needed)
                    float iv = sigf(vi);
                    float ov = sigf(vo);
                    float uv = __tanhf(vu);
                    float cv = iv * uv;
                    g_c[nx] = cv;
                    g_h[nx] = ov * __tanhf(cv);
                } else {
                    g_proj[0][nx] = vi;
                    g_proj[1][nx] = vf;
                    g_proj[2][nx] = vo;
                    g_proj[3][nx] = vu;
                }
            }
        }
    }
    __syncthreads();
    // publish level 0 (leaves done) to all 8 cluster peers
    if (tid == 0)
        for (unsigned r = 0; r < 8; r++) mbar_arrive_peer(mbar_base + 0 * 8, r);

    // ---- reload RECURRENT weight col-slices ------------------------------
    {
        const int jb2 = g * 32;
        for (int it = 0; it < 16; it++) {
            int k = it * 16 + (tid >> 5);
            int col = tid & 31;
            int didx = (k >> 2) * 128 + col * 4 + (k & 3);
            int sidx = k * Hv + jb2 + col;
            Wi4[didx] = W_ih[sidx];
            Wo4[didx] = W_oh[sidx];
            Wu4[didx] = W_uh[sidx];
            Wf4[didx] = W_fh[sidx];
        }
    }
    __syncthreads();

    // ---- bottom-up levels: adaptive batch, mbar wait/arrive per level ----
    {
        const int tmax = g_tmax[b];
        for (int lev = 1; lev <= tmax; lev++) {
            if (tid == 0) mbar_wait0(mbar_base + (lev - 1) * 8);
            __syncthreads();

            // (a) fh-phase: fh = W_fh . h for nodes of height lev-1
            {
                int pb = sm_tloff[lev - 1], pe = sm_tloff[lev];
                int pc = pe - pb;
                int cw = (pc + 15) >> 4; if (cw > 4) cw = 4; if (cw < 1) cw = 1;
                for (int i0 = pb + warp * cw; i0 < pe; i0 += 16 * cw) {
                    int mc = pe - i0; if (mc > cw) mc = cw;
                    if (mc == 1) {
                        int n = sm_tln[i0];
                        const float4* hsrc = (const float4*)(g_h + (size_t)n * Hv);
                        __syncwarp();
                        ((float4*)xw)[lane] = hsrc[lane];
                        ((float4*)xw)[lane + 32] = hsrc[lane + 32];
                        __syncwarp();
                        unsigned long long aX = 0, aY = 0;
                        #pragma unroll 8
                        for (int k4 = 0; k4 < 64; k4++) {
                            ulonglong2 wf = *(const ulonglong2*)&Wf4[k4 * 128 + lane * 4];
                            ulonglong2 xv = *(const ulonglong2*)&xw[k4 * 4];
                            FFMA2(aX, xv.x, wf.x); FFMA2(aY, xv.y, wf.y);
                        }
                        g_fh[(size_t)n * Hv + J] = pairsum(aX) + pairsum(aY);
                    } else {
                        int nid[4];
                        __syncwarp();
                        #pragma unroll
                        for (int mm = 0; mm < 4; mm++) {
                            if (mm < mc) {
                                int n = sm_tln[i0 + mm];
                                nid[mm] = n;
                                const float4* hsrc = (const float4*)(g_h + (size_t)n * Hv);
                                float4* dm = (float4*)(xw + mm * 256);
                                dm[lane] = hsrc[lane];
                                dm[lane + 32] = hsrc[lane + 32];
                            } else nid[mm] = -1;
                        }
                        __syncwarp();
                        unsigned long long af[4] = {0, 0, 0, 0};
                        #pragma unroll 4
                        for (int k4 = 0; k4 < 64; k4++) {
                            ulonglong2 wf = *(const ulonglong2*)&Wf4[k4 * 128 + lane * 4];
                            #pragma unroll
                            for (int mm = 0; mm < 4; mm++) {
                                ulonglong2 xv = *(const ulonglong2*)&xw[mm * 256 + k4 * 4];
                                FFMA2(af[mm], xv.x, wf.x); FFMA2(af[mm], xv.y, wf.y);
                            }
                        }
                        #pragma unroll
                        for (int mm = 0; mm < 4; mm++)
                            if (nid[mm] >= 0)
                                g_fh[(size_t)nid[mm] * Hv + J] = pairsum(af[mm]);
                    }
                }
            }
            __syncthreads();

            // (b) gate-phase: nodes of height lev, adaptive batch
            {
                int base = sm_tloff[lev], lend = sm_tloff[lev + 1];
                int cnt = lend - base;
                int cw = (cnt + 15) >> 4; if (cw > 4) cw = 4; if (cw < 1) cw = 1;
                for (int i0 = base + warp * cw; i0 < lend; i0 += 16 * cw) {
                    int mc = lend - i0; if (mc > cw) mc = cw;
                    if (mc == 1) {
                        int n = sm_tln[i0];
                        int nloc = n - b * Sv;
                        float fx = g_proj[1][(size_t)n * Hv + J];
                        int cs = sm_coff[nloc], ce = sm_coff[nloc + 1];
                        float4 s0 = make_float4(0, 0, 0, 0), s1 = make_float4(0, 0, 0, 0);
                        float fc = 0.0f;
                        for (int ci = cs; ci < ce; ci++) {
                            int ch = sm_child[ci];
                            const float4* hsrc = (const float4*)(g_h + (size_t)ch * Hv);
                            float4 v0 = hsrc[lane], v1 = hsrc[lane + 32];
                            s0.x += v0.x; s0.y += v0.y; s0.z += v0.z; s0.w += v0.w;
                            s1.x += v1.x; s1.y += v1.y; s1.z += v1.z; s1.w += v1.w;
                            fc += sigf(g_fh[(size_t)ch * Hv + J] + fx)
                                  * g_c[(size_t)ch * Hv + J];
                        }
                        __syncwarp();
                        ((float4*)xw)[lane] = s0; ((float4*)xw)[lane + 32] = s1;
                        __syncwarp();
                        unsigned long long ai = 0, aj = 0, ao = 0, ap = 0, au = 0, av = 0;
                        #pragma unroll 4
                        for (int k4 = 0; k4 < 64; k4++) {
                            ulonglong2 xv = *(const ulonglong2*)&xw[k4 * 4];
                            ulonglong2 wi = *(const ulonglong2*)&Wi4[k4 * 128 + lane * 4];
                            ulonglong2 wo = *(const ulonglong2*)&Wo4[k4 * 128 + lane * 4];
                            ulonglong2 wu = *(const ulonglong2*)&Wu4[k4 * 128 + lane * 4];
                            FFMA2(ai, xv.x, wi.x); FFMA2(aj, xv.y, wi.y);
                            FFMA2(ao, xv.x, wo.x); FFMA2(ap, xv.y, wo.y);
                            FFMA2(au, xv.x, wu.x); FFMA2(av, xv.y, wu.y);
                        }
                        size_t nx = (size_t)n * Hv + J;
                        float iv = sigf(g_proj[0][nx] + pairsum(ai) + pairsum(aj));
                        float ov = sigf(g_proj[2][nx] + pairsum(ao) + pairsum(ap));
                        float uv = __tanhf(g_proj[3][nx] + pairsum(au) + pairsum(av));
                        float cn = iv * uv + fc;
                        g_c[nx] = cn;
                        g_h[nx] = ov * __tanhf(cn);
                    } else {
                        int nid[4]; float fcv[4];
                        __syncwarp();
                        #pragma unroll
                        for (int mm = 0; mm < 4; mm++) {
                            fcv[mm] = 0.0f;
                            if (mm < mc) {
                                int n = sm_tln[i0 + mm];
                                nid[mm] = n;
                                int nloc = n - b * Sv;
                                float fx = g_proj[1][(size_t)n * Hv + J];
                                int cs = sm_coff[nloc], ce = sm_coff[nloc + 1];
                                float4 s0 = make_float4(0, 0, 0, 0);
                                float4 s1 = make_float4(0, 0, 0, 0);
                                float fc = 0.0f;
                                for (int ci = cs; ci < ce; ci++) {
                                    int ch = sm_child[ci];
                                    const float4* hsrc = (const float4*)(g_h + (size_t)ch * Hv);
                                    float4 v0 = hsrc[lane], v1 = hsrc[lane + 32];
                                    s0.x += v0.x; s0.y += v0.y; s0.z += v0.z; s0.w += v0.w;
                                    s1.x += v1.x; s1.y += v1.y; s1.z += v1.z; s1.w += v1.w;
                                    fc += sigf(g_fh[(size_t)ch * Hv + J] + fx)
                                          * g_c[(size_t)ch * Hv + J];
                                }
                                float4* dm = (float4*)(xw + mm * 256);
                                dm[lane] = s0; dm[lane + 32] = s1;
                                fcv[mm] = fc;
                            } else nid[mm] = -1;
                        }
                        __syncwarp();
                        unsigned long long ai[4] = {0, 0, 0, 0};
                        unsigned long long ao[4] = {0, 0, 0, 0};
                        unsigned long long au[4] = {0, 0, 0, 0};
                        #pragma unroll 2
                        for (int k4 = 0; k4 < 64; k4++) {
                            ulonglong2 wi = *(const ulonglong2*)&Wi4[k4 * 128 + lane * 4];
                            ulonglong2 wo = *(const ulonglong2*)&Wo4[k4 * 128 + lane * 4];
                            ulonglong2 wu = *(const ulonglong2*)&Wu4[k4 * 128 + lane * 4];
                            #pragma unroll
                            for (int mm = 0; mm < 4; mm++) {
                                ulonglong2 xv = *(const ulonglong2*)&xw[mm * 256 + k4 * 4];
                                FFMA2(ai[mm], xv.x, wi.x); FFMA2(ai[mm], xv.y, wi.y);
                                FFMA2(ao[mm], xv.x, wo.x); FFMA2(ao[mm], xv.y, wo.y);
                                FFMA2(au[mm], xv.x, wu.x); FFMA2(au[mm], xv.y, wu.y);
                            }
                        }
                        #pragma unroll
                        for (int mm = 0; mm < 4; mm++) {
                            if (nid[mm] < 0) continue;
                            size_t nx = (size_t)nid[mm] * Hv + J;
                            float iv = sigf(g_proj[0][nx] + pairsum(ai[mm]));
                            float ov = sigf(g_proj[2][nx] + pairsum(ao[mm]));
                            float uv = __tanhf(g_proj[3][nx] + pairsum(au[mm]));
                            float cn = iv * uv + fcv[mm];
                            g_c[nx] = cn;
                            g_h[nx] = ov * __tanhf(cn);
                        }
                    }
                }
            }
            __syncthreads();
            if (tid == 0 && lev < tmax)
                for (unsigned r = 0; r < 8; r++) mbar_arrive_peer(mbar_base + lev * 8, r);
        }
    }

    // ---- pooling (column-local: only own-CTA data needed) + head ---------
    __syncthreads();
    {
        float m = -1e30f;
        for (int s2 = warp; s2 < Sv; s2 += 16)
            m = fmaxf(m, g_h[(size_t)(b * Sv + s2) * Hv + J]);
        scratch[warp * 32 + lane] = m;
        __syncthreads();
        if (tid < 32) {
            float mm = scratch[tid];
            #pragma unroll
            for (int r = 1; r < 16; r++) mm = fmaxf(mm, scratch[r * 32 + tid]);
            g_pooled[b * Hv + g * 32 + tid] = mm;
        }
        __syncthreads();
        if (tid == 0) red_add_rel(&g_pdone[b * 32], 1u);
    }
    if (g == 0) {
        if (tid == 0) { while (ld_acq(&g_pdone[b * 32]) < 8u) { } }
        __syncthreads();
        if (warp < Lv) {
            float acc = 0.0f;
            for (int k = lane; k < Hv; k += 32)
                acc += g_pooled[b * Hv + k] * W_out[k * Lv + warp];
            #pragma unroll
            for (int off = 16; off; off >>= 1)
                acc += __shfl_down_sync(0xFFFFFFFFu, acc, off);
            if (lane == 0) out[b * Lv + warp] = acc + b_out[warp];
        }
    }
}

// ---------------- launch --------------------------------------------------
extern "C" void kernel_launch(void* const* d_in, const int* in_sizes, int n_in,
                              void* d_out, int out_size) {
    const int s = (n_in >= 22) ? 1 : 0;   // robust to n_levels scalar presence
    const int* xs          = (const int*)d_in[0];
    const int* rels        = (const int*)d_in[1];
    const int* child_idx   = (const int*)d_in[2];
    const int* parent_idx  = (const int*)d_in[3];
    const int* node_height = (const int*)d_in[4];
    const float* emb_W = (const float*)d_in[5 + s];
    const float* rel_W = (const float*)d_in[6 + s];
    const float* W_ix  = (const float*)d_in[7 + s];
    const float* b_ix  = (const float*)d_in[8 + s];
    const float* W_ih  = (const float*)d_in[9 + s];
    const float* b_ih  = (const float*)d_in[10 + s];
    const float* W_fx  = (const float*)d_in[11 + s];
    const float* b_fx  = (const float*)d_in[12 + s];
    const float* W_fh  = (const float*)d_in[13 + s];
    const float* b_fh  = (const float*)d_in[14 + s];
    const float* W_ox  = (const float*)d_in[15 + s];
    const float* W_oh  = (const float*)d_in[16 + s];
    const float* W_ux  = (const float*)d_in[17 + s];
    const float* W_uh  = (const float*)d_in[18 + s];
    const float* W_out = (const float*)d_in[19 + s];
    const float* b_out = (const float*)d_in[20 + s];
    float* out = (float*)d_out;

    cudaFuncSetAttribute(main_kernel, cudaFuncAttributeMaxDynamicSharedMemorySize, SMEM_BYTES);

    setup_kernel<<<1, 1024>>>(child_idx, parent_idx, node_height);
    main_kernel<<<NCTA, NTHR, SMEM_BYTES>>>(xs, rels, node_height, emb_W, rel_W,
                                            W_ix, b_ix, W_ih, b_ih,
                                            W_fx, b_fx, W_fh, b_fh,
                                            W_ox, W_oh, W_ux, W_uh,
                                            W_out, b_out, out);
}

// round 13
// speedup vs baseline: 1.5536x; 1.5536x over previous
#include <cuda_runtime.h>

#define Nn   2048      // B*S
#define Bv   16
#define Sv   128
#define Hv   256
#define DINv 256
#define DEv  192
#define DRv  64
#define Ev   2032      // B*(S-1)
#define Lv   12
#define NCTA 128       // 16 trees x 8 column groups
#define NTHR 512
#define NLEVF 24
#define SMEM_BYTES 198656   // 32768 wt + 16384 scratch floats + 512 ints meta

// packed fp32x2 FMA (sm_103a FFMA2)
#define FFMA2(acc, a, b) asm("fma.rn.f32x2 %0, %1, %2, %0;" : "+l"(acc) : "l"(a), "l"(b))

__device__ __forceinline__ float pairsum(unsigned long long v) {
    float lo, hi;
    asm("mov.b64 {%0, %1}, %2;" : "=f"(lo), "=f"(hi) : "l"(v));
    return lo + hi;
}

// ---------------- device scratch (no allocations allowed) ----------------
__device__ float g_proj[4][Nn * Hv];   // i(+bi+bih), f(+bf+bfh), o, u  (column-local)
__device__ float g_h[Nn * Hv];
__device__ float g_c[Nn * Hv];         // column-local
__device__ float g_fh[Nn * Hv];        // W_fh . h  (column-local)
__device__ float g_pooled[Bv * Hv];
__device__ int   g_coff[Nn + 1];
__device__ int   g_children[Ev];
__device__ int   g_tl_off[512];        // [16][32] per-tree level offsets
__device__ int   g_tl_nodes[Nn];
__device__ int   g_tmax[Bv];
__device__ unsigned g_lflag[Bv * NLEVF * 8];  // per-tree per-level per-CTA flag
__device__ unsigned g_pdone[Bv * 32];

// fence-free release/acquire primitives (no CCTL.IVALL -> L1 stays warm)
__device__ __forceinline__ unsigned ld_acq(unsigned* p) {
    unsigned v;
    asm volatile("ld.acquire.gpu.global.u32 %0, [%1];" : "=r"(v) : "l"(p) : "memory");
    return v;
}
__device__ __forceinline__ void st_rel(unsigned* p, unsigned v) {
    asm volatile("st.release.gpu.global.u32 [%0], %1;" :: "l"(p), "r"(v) : "memory");
}
__device__ __forceinline__ void red_add_rel(unsigned* p, unsigned v) {
    asm volatile("red.release.gpu.global.add.u32 [%0], %1;" :: "l"(p), "r"(v) : "memory");
}

__device__ __forceinline__ float sigf(float x) {
    return 1.0f / (1.0f + __expf(-x));
}

// ---------------- setup: CSR + per-tree level buckets + flag reset --------
__global__ void setup_kernel(const int* __restrict__ child_idx,
                             const int* __restrict__ parent_idx,
                             const int* __restrict__ node_height) {
    __shared__ int cnt[Nn];
    __shared__ int psm[Ev];
    __shared__ int hsm[Nn];
    __shared__ int part[256];
    __shared__ int lvl[512];
    __shared__ int lfill[512];
    __shared__ int loff[512];
    const int tid = threadIdx.x;               // 1024 threads
    for (int i = tid; i < Nn; i += 1024) { cnt[i] = 0; hsm[i] = node_height[i]; }
    for (int i = tid; i < Ev; i += 1024) psm[i] = parent_idx[i];
    for (int i = tid; i < 512; i += 1024) { lvl[i] = 0; lfill[i] = 0; }
    for (int i = tid; i < Bv * NLEVF * 8; i += 1024) g_lflag[i] = 0u;
    if (tid < Bv) g_pdone[tid * 32] = 0u;
    __syncthreads();
    for (int e = tid; e < Ev; e += 1024) atomicAdd(&cnt[psm[e]], 1);
    for (int n = tid; n < Nn; n += 1024) atomicAdd(&lvl[(n >> 7) * 32 + hsm[n]], 1);
    __syncthreads();
    if (tid < 256) { int s = 0; for (int i = 0; i < 8; i++) s += cnt[tid * 8 + i]; part[tid] = s; }
    __syncthreads();
    if (tid == 0) {
        int run = 0;
        for (int i = 0; i < 256; i++) { int v = part[i]; part[i] = run; run += v; }
    }
    if (tid < 16) {                            // per-tree level prefix + maxlev
        int run = 0, mx = 1;
        for (int l = 0; l < 32; l++) {
            loff[tid * 32 + l] = tid * 128 + run;
            if (lvl[tid * 32 + l] > 0) mx = l;
            run += lvl[tid * 32 + l];
        }
        g_tmax[tid] = mx;
    }
    __syncthreads();
    for (int i = tid; i < 512; i += 1024) g_tl_off[i] = loff[i];
    if (tid < 256) {
        int run = part[tid];
        for (int i = 0; i < 8; i++) { int idx = tid * 8 + i; g_coff[idx] = run; run += cnt[idx]; }
        if (tid == 255) g_coff[Nn] = run;
    }
    __syncthreads();
    // deterministic CSR scatter: rank = #earlier same-parent edges (same batch)
    for (int e = tid; e < Ev; e += 1024) {
        int p = psm[e];
        int bstart = (e / (Sv - 1)) * (Sv - 1);
        int rank = 0;
        for (int e2 = bstart; e2 < e; e2++) rank += (psm[e2] == p);
        g_children[g_coff[p] + rank] = child_idx[e];
    }
    // per-tree level bucket fill (intra-level order numerically irrelevant)
    for (int n = tid; n < Nn; n += 1024) {
        int key = (n >> 7) * 32 + hsm[n];
        int r = atomicAdd(&lfill[key], 1);
        g_tl_nodes[loff[key] + r] = n;
    }
}

// ---------------- persistent kernel: R11 skeleton + leaf fusion ----------
__global__ void __launch_bounds__(NTHR, 1)
main_kernel(const int* __restrict__ xs, const int* __restrict__ rels,
            const int* __restrict__ nheight,
            const float* __restrict__ emb_W, const float* __restrict__ rel_W,
            const float* __restrict__ W_ix, const float* __restrict__ b_ix,
            const float* __restrict__ W_ih, const float* __restrict__ b_ih,
            const float* __restrict__ W_fx, const float* __restrict__ b_fx,
            const float* __restrict__ W_fh, const float* __restrict__ b_fh,
            const float* __restrict__ W_ox, const float* __restrict__ W_oh,
            const float* __restrict__ W_ux, const float* __restrict__ W_uh,
            const float* __restrict__ W_out, const float* __restrict__ b_out,
            float* __restrict__ out) {
    extern __shared__ float sm[];
    float* Wi4 = sm;                  // col-slice layout [(k>>2)*128 + col*4 + (k&3)]
    float* Wo4 = sm + 8192;
    float* Wu4 = sm + 16384;
    float* Wf4 = sm + 24576;
    float* scratch = sm + 32768;      // 16384 floats = 16 warps x 1024
    int*   meta = (int*)(sm + 49152); // 512 ints
    int* sm_tloff = meta;             // 33
    int* sm_tln   = meta + 33;        // 128 node ids (global)
    int* sm_coff  = meta + 161;       // 129, rebased
    int* sm_child = meta + 290;       // <=127 child node ids (global)

    const int tid  = threadIdx.x;
    const int lane = tid & 31;
    const int warp = tid >> 5;
    const int blk  = blockIdx.x;
    const int b    = blk >> 3;        // tree id
    const int g    = blk & 7;         // column group
    const int J    = g * 32 + lane;
    float* xw = scratch + warp * 1024; // 4 nodes x 256 staging

    // ---- phase 0: weights (input-side) + tree metadata -> smem -----------
    {
        const int jb2 = g * 32;
        for (int it = 0; it < 16; it++) {
            int k = it * 16 + (tid >> 5);
            int col = tid & 31;
            int didx = (k >> 2) * 128 + col * 4 + (k & 3);
            int sidx = k * Hv + jb2 + col;
            Wi4[didx] = W_ix[sidx];
            Wo4[didx] = W_ox[sidx];
            Wu4[didx] = W_ux[sidx];
            Wf4[didx] = W_fx[sidx];
        }
        if (tid < 32) sm_tloff[tid] = g_tl_off[b * 32 + tid] - b * 128;
        if (tid >= 32 && tid < 160) sm_tln[tid - 32] = g_tl_nodes[b * 128 + (tid - 32)];
        int cbase = g_coff[b * 128];
        int cend  = g_coff[b * 128 + 128];
        if (tid >= 160 && tid < 289) sm_coff[tid - 160] = g_coff[b * 128 + (tid - 160)] - cbase;
        for (int i = tid; i < cend - cbase; i += NTHR) sm_child[i] = g_children[cbase + i];
    }
    const float bi = b_ix[J] + b_ih[J];
    const float bf = b_fx[J] + b_fh[J];
    __syncthreads();

    // ---- P1: 4 projections, 4 nodes/warp-iter; LEAVES FINISHED INLINE ----
    {
        for (int t = 0; t < 2; t++) {
            int nb = b * Sv + (warp + t * 16) * 4;   // 4 contiguous nodes
            int hgt0 = nheight[nb + 0], hgt1 = nheight[nb + 1];
            int hgt2 = nheight[nb + 2], hgt3 = nheight[nb + 3];
            __syncwarp();
            #pragma unroll
            for (int mm = 0; mm < 4; mm++) {
                int n = nb + mm;
                const float4* er = (const float4*)(emb_W + (size_t)xs[n] * DEv);
                const float4* rr = (const float4*)(rel_W + (size_t)rels[n] * DRv);
                float4 a = er[lane];
                float4 bb = (lane < 16) ? er[lane + 32] : rr[lane - 16];
                float4* dm = (float4*)(xw + mm * 256);
                dm[lane] = a; dm[lane + 32] = bb;
            }
            __syncwarp();
            unsigned long long acc[16];
            #pragma unroll
            for (int q = 0; q < 16; q++) acc[q] = 0ull;
            #pragma unroll 4
            for (int k4 = 0; k4 < 64; k4++) {
                ulonglong2 wi = *(const ulonglong2*)&Wi4[k4 * 128 + lane * 4];
                ulonglong2 wf = *(const ulonglong2*)&Wf4[k4 * 128 + lane * 4];
                ulonglong2 wo = *(const ulonglong2*)&Wo4[k4 * 128 + lane * 4];
                ulonglong2 wu = *(const ulonglong2*)&Wu4[k4 * 128 + lane * 4];
                #pragma unroll
                for (int mm = 0; mm < 4; mm++) {
                    ulonglong2 xv = *(const ulonglong2*)&xw[mm * 256 + k4 * 4];
                    FFMA2(acc[mm * 4 + 0], xv.x, wi.x); FFMA2(acc[mm * 4 + 0], xv.y, wi.y);
                    FFMA2(acc[mm * 4 + 1], xv.x, wf.x); FFMA2(acc[mm * 4 + 1], xv.y, wf.y);
                    FFMA2(acc[mm * 4 + 2], xv.x, wo.x); FFMA2(acc[mm * 4 + 2], xv.y, wo.y);
                    FFMA2(acc[mm * 4 + 3], xv.x, wu.x); FFMA2(acc[mm * 4 + 3], xv.y, wu.y);
                }
            }
            #pragma unroll
            for (int mm = 0; mm < 4; mm++) {
                int hgt = (mm == 0) ? hgt0 : (mm == 1) ? hgt1 : (mm == 2) ? hgt2 : hgt3;
                size_t nx = (size_t)(nb + mm) * Hv + J;
                float vi = pairsum(acc[mm * 4 + 0]) + bi;
                float vf = pairsum(acc[mm * 4 + 1]) + bf;
                float vo = pairsum(acc[mm * 4 + 2]);
                float vu = pairsum(acc[mm * 4 + 3]);
                if (hgt == 0) {
                    // leaf: finish the whole cell now (no proj stores needed)
                    float iv = sigf(vi);
                    float ov = sigf(vo);
                    float uv = __tanhf(vu);
                    float cv = iv * uv;
                    g_c[nx] = cv;
                    g_h[nx] = ov * __tanhf(cv);
                } else {
                    g_proj[0][nx] = vi;
                    g_proj[1][nx] = vf;
                    g_proj[2][nx] = vo;
                    g_proj[3][nx] = vu;
                }
            }
        }
    }
    __syncthreads();
    // publish level 0 immediately (peers can start level 1 while we reload)
    if (tid == 0) st_rel(&g_lflag[(b * NLEVF + 0) * 8 + g], 1u);

    // ---- reload RECURRENT weight col-slices ------------------------------
    {
        const int jb2 = g * 32;
        for (int it = 0; it < 16; it++) {
            int k = it * 16 + (tid >> 5);
            int col = tid & 31;
            int didx = (k >> 2) * 128 + col * 4 + (k & 3);
            int sidx = k * Hv + jb2 + col;
            Wi4[didx] = W_ih[sidx];
            Wo4[didx] = W_oh[sidx];
            Wu4[didx] = W_uh[sidx];
            Wf4[didx] = W_fh[sidx];
        }
    }
    __syncthreads();

    // ---- bottom-up levels: adaptive batch, one flag per level ------------
    {
        const int tmax = g_tmax[b];
        for (int lev = 1; lev <= tmax; lev++) {
            // one-hop wait: all 8 CTAs of my tree published level lev-1
            if (warp == 0) {
                unsigned* fp = &g_lflag[(b * NLEVF + lev - 1) * 8 + (lane & 7)];
                for (;;) {
                    unsigned d = (lane < 8) ? ld_acq(fp) : 1u;
                    if (__all_sync(0xFFFFFFFFu, d != 0u)) break;
                }
            }
            __syncthreads();

            // (a) fh-phase: fh = W_fh . h for nodes of height lev-1
            {
                int pb = sm_tloff[lev - 1], pe = sm_tloff[lev];
                int pc = pe - pb;
                int cw = (pc + 15) >> 4; if (cw > 4) cw = 4; if (cw < 1) cw = 1;
                for (int i0 = pb + warp * cw; i0 < pe; i0 += 16 * cw) {
                    int mc = pe - i0; if (mc > cw) mc = cw;
                    if (mc == 1) {
                        int n = sm_tln[i0];
                        const float4* hsrc = (const float4*)(g_h + (size_t)n * Hv);
                        __syncwarp();
                        ((float4*)xw)[lane] = hsrc[lane];
                        ((float4*)xw)[lane + 32] = hsrc[lane + 32];
                        __syncwarp();
                        unsigned long long aX = 0, aY = 0;
                        #pragma unroll 8
                        for (int k4 = 0; k4 < 64; k4++) {
                            ulonglong2 wf = *(const ulonglong2*)&Wf4[k4 * 128 + lane * 4];
                            ulonglong2 xv = *(const ulonglong2*)&xw[k4 * 4];
                            FFMA2(aX, xv.x, wf.x); FFMA2(aY, xv.y, wf.y);
                        }
                        g_fh[(size_t)n * Hv + J] = pairsum(aX) + pairsum(aY);
                    } else {
                        int nid[4];
                        __syncwarp();
                        #pragma unroll
                        for (int mm = 0; mm < 4; mm++) {
                            if (mm < mc) {
                                int n = sm_tln[i0 + mm];
                                nid[mm] = n;
                                const float4* hsrc = (const float4*)(g_h + (size_t)n * Hv);
                                float4* dm = (float4*)(xw + mm * 256);
                                dm[lane] = hsrc[lane];
                                dm[lane + 32] = hsrc[lane + 32];
                            } else nid[mm] = -1;
                        }
                        __syncwarp();
                        unsigned long long af[4] = {0, 0, 0, 0};
                        #pragma unroll 4
                        for (int k4 = 0; k4 < 64; k4++) {
                            ulonglong2 wf = *(const ulonglong2*)&Wf4[k4 * 128 + lane * 4];
                            #pragma unroll
                            for (int mm = 0; mm < 4; mm++) {
                                ulonglong2 xv = *(const ulonglong2*)&xw[mm * 256 + k4 * 4];
                                FFMA2(af[mm], xv.x, wf.x); FFMA2(af[mm], xv.y, wf.y);
                            }
                        }
                        #pragma unroll
                        for (int mm = 0; mm < 4; mm++)
                            if (nid[mm] >= 0)
                                g_fh[(size_t)nid[mm] * Hv + J] = pairsum(af[mm]);
                    }
                }
            }
            __syncthreads();

            // (b) gate-phase: nodes of height lev, adaptive batch
            {
                int base = sm_tloff[lev], lend = sm_tloff[lev + 1];
                int cnt = lend - base;
                int cw = (cnt + 15) >> 4; if (cw > 4) cw = 4; if (cw < 1) cw = 1;
                for (int i0 = base + warp * cw; i0 < lend; i0 += 16 * cw) {
                    int mc = lend - i0; if (mc > cw) mc = cw;
                    if (mc == 1) {
                        int n = sm_tln[i0];
                        int nloc = n - b * Sv;
                        float fx = g_proj[1][(size_t)n * Hv + J];
                        int cs = sm_coff[nloc], ce = sm_coff[nloc + 1];
                        float4 s0 = make_float4(0, 0, 0, 0), s1 = make_float4(0, 0, 0, 0);
                        float fc = 0.0f;
                        for (int ci = cs; ci < ce; ci++) {
                            int ch = sm_child[ci];
                            const float4* hsrc = (const float4*)(g_h + (size_t)ch * Hv);
                            float4 v0 = hsrc[lane], v1 = hsrc[lane + 32];
                            s0.x += v0.x; s0.y += v0.y; s0.z += v0.z; s0.w += v0.w;
                            s1.x += v1.x; s1.y += v1.y; s1.z += v1.z; s1.w += v1.w;
                            fc += sigf(g_fh[(size_t)ch * Hv + J] + fx)
                                  * g_c[(size_t)ch * Hv + J];
                        }
                        __syncwarp();
                        ((float4*)xw)[lane] = s0; ((float4*)xw)[lane + 32] = s1;
                        __syncwarp();
                        unsigned long long ai = 0, aj = 0, ao = 0, ap = 0, au = 0, av = 0;
                        #pragma unroll 4
                        for (int k4 = 0; k4 < 64; k4++) {
                            ulonglong2 xv = *(const ulonglong2*)&xw[k4 * 4];
                            ulonglong2 wi = *(const ulonglong2*)&Wi4[k4 * 128 + lane * 4];
                            ulonglong2 wo = *(const ulonglong2*)&Wo4[k4 * 128 + lane * 4];
                            ulonglong2 wu = *(const ulonglong2*)&Wu4[k4 * 128 + lane * 4];
                            FFMA2(ai, xv.x, wi.x); FFMA2(aj, xv.y, wi.y);
                            FFMA2(ao, xv.x, wo.x); FFMA2(ap, xv.y, wo.y);
                            FFMA2(au, xv.x, wu.x); FFMA2(av, xv.y, wu.y);
                        }
                        size_t nx = (size_t)n * Hv + J;
                        float iv = sigf(g_proj[0][nx] + pairsum(ai) + pairsum(aj));
                        float ov = sigf(g_proj[2][nx] + pairsum(ao) + pairsum(ap));
                        float uv = __tanhf(g_proj[3][nx] + pairsum(au) + pairsum(av));
                        float cn = iv * uv + fc;
                        g_c[nx] = cn;
                        g_h[nx] = ov * __tanhf(cn);
                    } else {
                        int nid[4]; float fcv[4];
                        __syncwarp();
                        #pragma unroll
                        for (int mm = 0; mm < 4; mm++) {
                            fcv[mm] = 0.0f;
                            if (mm < mc) {
                                int n = sm_tln[i0 + mm];
                                nid[mm] = n;
                                int nloc = n - b * Sv;
                                float fx = g_proj[1][(size_t)n * Hv + J];
                                int cs = sm_coff[nloc], ce = sm_coff[nloc + 1];
                                float4 s0 = make_float4(0, 0, 0, 0);
                                float4 s1 = make_float4(0, 0, 0, 0);
                                float fc = 0.0f;
                                for (int ci = cs; ci < ce; ci++) {
                                    int ch = sm_child[ci];
                                    const float4* hsrc = (const float4*)(g_h + (size_t)ch * Hv);
                                    float4 v0 = hsrc[lane], v1 = hsrc[lane + 32];
                                    s0.x += v0.x; s0.y += v0.y; s0.z += v0.z; s0.w += v0.w;
                                    s1.x += v1.x; s1.y += v1.y; s1.z += v1.z; s1.w += v1.w;
                                    fc += sigf(g_fh[(size_t)ch * Hv + J] + fx)
                                          * g_c[(size_t)ch * Hv + J];
                                }
                                float4* dm = (float4*)(xw + mm * 256);
                                dm[lane] = s0; dm[lane + 32] = s1;
                                fcv[mm] = fc;
                            } else nid[mm] = -1;
                        }
                        __syncwarp();
                        unsigned long long ai[4] = {0, 0, 0, 0};
                        unsigned long long ao[4] = {0, 0, 0, 0};
                        unsigned long long au[4] = {0, 0, 0, 0};
                        #pragma unroll 2
                        for (int k4 = 0; k4 < 64; k4++) {
                            ulonglong2 wi = *(const ulonglong2*)&Wi4[k4 * 128 + lane * 4];
                            ulonglong2 wo = *(const ulonglong2*)&Wo4[k4 * 128 + lane * 4];
                            ulonglong2 wu = *(const ulonglong2*)&Wu4[k4 * 128 + lane * 4];
                            #pragma unroll
                            for (int mm = 0; mm < 4; mm++) {
                                ulonglong2 xv = *(const ulonglong2*)&xw[mm * 256 + k4 * 4];
                                FFMA2(ai[mm], xv.x, wi.x); FFMA2(ai[mm], xv.y, wi.y);
                                FFMA2(ao[mm], xv.x, wo.x); FFMA2(ao[mm], xv.y, wo.y);
                                FFMA2(au[mm], xv.x, wu.x); FFMA2(au[mm], xv.y, wu.y);
                            }
                        }
                        #pragma unroll
                        for (int mm = 0; mm < 4; mm++) {
                            if (nid[mm] < 0) continue;
                            size_t nx = (size_t)nid[mm] * Hv + J;
                            float iv = sigf(g_proj[0][nx] + pairsum(ai[mm]));
                            float ov = sigf(g_proj[2][nx] + pairsum(ao[mm]));
                            float uv = __tanhf(g_proj[3][nx] + pairsum(au[mm]));
                            float cn = iv * uv + fcv[mm];
                            g_c[nx] = cn;
                            g_h[nx] = ov * __tanhf(cn);
                        }
                    }
                }
            }
            __syncthreads();
            if (tid == 0) st_rel(&g_lflag[(b * NLEVF + lev) * 8 + g], 1u);
        }
    }

    // ---- pooling (column-local) + head -----------------------------------
    __syncthreads();
    {
        float m = -1e30f;
        for (int s2 = warp; s2 < Sv; s2 += 16)
            m = fmaxf(m, g_h[(size_t)(b * Sv + s2) * Hv + J]);
        scratch[warp * 32 + lane] = m;
        __syncthreads();
        if (tid < 32) {
            float mm = scratch[tid];
            #pragma unroll
            for (int r = 1; r < 16; r++) mm = fmaxf(mm, scratch[r * 32 + tid]);
            g_pooled[b * Hv + g * 32 + tid] = mm;
        }
        __syncthreads();
        if (tid == 0) red_add_rel(&g_pdone[b * 32], 1u);
    }
    if (g == 0) {
        if (tid == 0) { while (ld_acq(&g_pdone[b * 32]) < 8u) { } }
        __syncthreads();
        if (warp < Lv) {
            float acc = 0.0f;
            for (int k = lane; k < Hv; k += 32)
                acc += g_pooled[b * Hv + k] * W_out[k * Lv + warp];
            #pragma unroll
            for (int off = 16; off; off >>= 1)
                acc += __shfl_down_sync(0xFFFFFFFFu, acc, off);
            if (lane == 0) out[b * Lv + warp] = acc + b_out[warp];
        }
    }
}

// ---------------- launch --------------------------------------------------
extern "C" void kernel_launch(void* const* d_in, const int* in_sizes, int n_in,
                              void* d_out, int out_size) {
    const int s = (n_in >= 22) ? 1 : 0;   // robust to n_levels scalar presence
    const int* xs          = (const int*)d_in[0];
    const int* rels        = (const int*)d_in[1];
    const int* child_idx   = (const int*)d_in[2];
    const int* parent_idx  = (const int*)d_in[3];
    const int* node_height = (const int*)d_in[4];
    const float* emb_W = (const float*)d_in[5 + s];
    const float* rel_W = (const float*)d_in[6 + s];
    const float* W_ix  = (const float*)d_in[7 + s];
    const float* b_ix  = (const float*)d_in[8 + s];
    const float* W_ih  = (const float*)d_in[9 + s];
    const float* b_ih  = (const float*)d_in[10 + s];
    const float* W_fx  = (const float*)d_in[11 + s];
    const float* b_fx  = (const float*)d_in[12 + s];
    const float* W_fh  = (const float*)d_in[13 + s];
    const float* b_fh  = (const float*)d_in[14 + s];
    const float* W_ox  = (const float*)d_in[15 + s];
    const float* W_oh  = (const float*)d_in[16 + s];
    const float* W_ux  = (const float*)d_in[17 + s];
    const float* W_uh  = (const float*)d_in[18 + s];
    const float* W_out = (const float*)d_in[19 + s];
    const float* b_out = (const float*)d_in[20 + s];
    float* out = (float*)d_out;

    cudaFuncSetAttribute(main_kernel, cudaFuncAttributeMaxDynamicSharedMemorySize, SMEM_BYTES);

    setup_kernel<<<1, 1024>>>(child_idx, parent_idx, node_height);
    main_kernel<<<NCTA, NTHR, SMEM_BYTES>>>(xs, rels, node_height, emb_W, rel_W,
                                            W_ix, b_ix, W_ih, b_ih,
                                            W_fx, b_fx, W_fh, b_fh,
                                            W_ox, W_oh, W_ux, W_uh,
                                            W_out, b_out, out);
}

// round 15
// speedup vs baseline: 1.6419x; 1.0569x over previous
#include <cuda_runtime.h>

#define Nn   2048      // B*S
#define Bv   16
#define Sv   128
#define Hv   256
#define DINv 256
#define DEv  192
#define DRv  64
#define Ev   2032      // B*(S-1)
#define Lv   12
#define NCTA 128       // 16 trees x 8 column groups
#define NTHR 512
#define NLEVF 24
#define SMEM_BYTES 198656   // 32768 wt + 16384 scratch floats + 512 ints meta

// packed fp32x2 FMA (sm_103a FFMA2)
#define FFMA2(acc, a, b) asm("fma.rn.f32x2 %0, %1, %2, %0;" : "+l"(acc) : "l"(a), "l"(b))

__device__ __forceinline__ float pairsum(unsigned long long v) {
    float lo, hi;
    asm("mov.b64 {%0, %1}, %2;" : "=f"(lo), "=f"(hi) : "l"(v));
    return lo + hi;
}

// ---------------- device scratch (no allocations allowed) ----------------
__device__ float g_proj[4][Nn * Hv];   // i(+bi+bih), f(+bf+bfh), o, u  (column-local)
__device__ float g_h[Nn * Hv];
__device__ float g_c[Nn * Hv];         // column-local
__device__ float g_fh[Nn * Hv];        // W_fh . h  (column-local)
__device__ float g_pooled[Bv * Hv];
__device__ int   g_coff[Nn + 1];
__device__ int   g_children[Ev];
__device__ int   g_tl_off[512];        // [16][32] per-tree level offsets
__device__ int   g_tl_nodes[Nn];
__device__ int   g_tmax[Bv];
__device__ unsigned g_lflag[Bv * NLEVF * 8];  // per-tree per-level per-CTA flag
__device__ unsigned g_pdone[Bv * 32];

// flag publish: release (drains h stores to L2 first)
__device__ __forceinline__ void st_rel(unsigned* p, unsigned v) {
    asm volatile("st.release.gpu.global.u32 [%0], %1;" :: "l"(p), "r"(v) : "memory");
}
__device__ __forceinline__ void red_add_rel(unsigned* p, unsigned v) {
    asm volatile("red.release.gpu.global.add.u32 [%0], %1;" :: "l"(p), "r"(v) : "memory");
}
// flag poll: L2-direct, NO acquire (avoids per-level L1 invalidation).
// Safe: cross-CTA data lines (g_h rows; each 128B line = one CTA's column
// block) are first-touched only after their flag, so no stale L1 copies can
// exist; producer's release guarantees L2 visibility.
__device__ __forceinline__ unsigned ld_cg(unsigned* p) {
    unsigned v;
    asm volatile("ld.global.cg.u32 %0, [%1];" : "=r"(v) : "l"(p) : "memory");
    return v;
}

__device__ __forceinline__ float sigf(float x) {
    return 1.0f / (1.0f + __expf(-x));
}

// ---------------- setup: per-tree (16 CTAs), CSR + buckets + flag reset ---
__global__ void setup_kernel(const int* __restrict__ child_idx,
                             const int* __restrict__ parent_idx,
                             const int* __restrict__ node_height) {
    __shared__ int hs[Sv];
    __shared__ int par[Sv];        // parent local id per edge (127 used)
    __shared__ int cnt[Sv];
    __shared__ int coff_l[Sv + 1];
    __shared__ int lvl[32];
    __shared__ int lfill[32];
    __shared__ int loff[32];
    const int b   = blockIdx.x;    // tree id
    const int tid = threadIdx.x;   // 128 threads
    const int E1  = Sv - 1;        // 127 edges per tree

    if (tid < Sv) { hs[tid] = (int)node_height[b * Sv + tid]; cnt[tid] = 0; }
    if (tid < 32) { lvl[tid] = 0; lfill[tid] = 0; }
    if (tid < E1) par[tid] = (int)parent_idx[b * E1 + tid] - b * Sv;
    // reset flags for this tree
    for (int i = tid; i < NLEVF * 8; i += 128) g_lflag[b * NLEVF * 8 + i] = 0u;
    if (tid == 0) g_pdone[b * 32] = 0u;
    if (tid == 0 && b == Bv - 1) g_coff[Nn] = Ev;   // BUGFIX: tail sentinel
    __syncthreads();
    if (tid < E1) atomicAdd(&cnt[par[tid]], 1);
    if (tid < Sv) atomicAdd(&lvl[hs[tid]], 1);
    __syncthreads();
    if (tid == 0) {
        int run = 0;
        for (int i = 0; i < Sv; i++) { coff_l[i] = run; run += cnt[i]; }
        coff_l[Sv] = run;
        int run2 = 0, mx = 1;
        for (int l = 0; l < 32; l++) {
            loff[l] = run2;
            if (lvl[l] > 0) mx = l;
            run2 += lvl[l];
        }
        g_tmax[b] = mx;
    }
    __syncthreads();
    // global CSR offsets (tree b owns children slots [b*127, (b+1)*127))
    if (tid < Sv) g_coff[b * Sv + tid] = b * E1 + coff_l[tid];
    if (tid < 32) g_tl_off[b * 32 + tid] = b * Sv + loff[tid];
    // deterministic CSR scatter: rank = #earlier same-parent edges
    if (tid < E1) {
        int p = par[tid];
        int rank = 0;
        for (int e2 = 0; e2 < tid; e2++) rank += (par[e2] == p);
        g_children[b * E1 + coff_l[p] + rank] = (int)child_idx[b * E1 + tid];
    }
    // level bucket fill (intra-level order numerically irrelevant)
    if (tid < Sv) {
        int h = hs[tid];
        int r = atomicAdd(&lfill[h], 1);
        g_tl_nodes[b * Sv + loff[h] + r] = b * Sv + tid;
    }
}

// ---------------- persistent kernel: R13 skeleton, cg-poll ---------------
__global__ void __launch_bounds__(NTHR, 1)
main_kernel(const int* __restrict__ xs, const int* __restrict__ rels,
            const int* __restrict__ nheight,
            const float* __restrict__ emb_W, const float* __restrict__ rel_W,
            const float* __restrict__ W_ix, const float* __restrict__ b_ix,
            const float* __restrict__ W_ih, const float* __restrict__ b_ih,
            const float* __restrict__ W_fx, const float* __restrict__ b_fx,
            const float* __restrict__ W_fh, const float* __restrict__ b_fh,
            const float* __restrict__ W_ox, const float* __restrict__ W_oh,
            const float* __restrict__ W_ux, const float* __restrict__ W_uh,
            const float* __restrict__ W_out, const float* __restrict__ b_out,
            float* __restrict__ out) {
    extern __shared__ float sm[];
    float* Wi4 = sm;                  // col-slice layout [(k>>2)*128 + col*4 + (k&3)]
    float* Wo4 = sm + 8192;
    float* Wu4 = sm + 16384;
    float* Wf4 = sm + 24576;
    float* scratch = sm + 32768;      // 16384 floats = 16 warps x 1024
    int*   meta = (int*)(sm + 49152); // 512 ints
    int* sm_tloff = meta;             // 33
    int* sm_tln   = meta + 33;        // 128 node ids (global)
    int* sm_coff  = meta + 161;       // 129, rebased
    int* sm_child = meta + 290;       // <=127 child node ids (global)

    const int tid  = threadIdx.x;
    const int lane = tid & 31;
    const int warp = tid >> 5;
    const int blk  = blockIdx.x;
    const int b    = blk >> 3;        // tree id
    const int g    = blk & 7;         // column group
    const int J    = g * 32 + lane;
    float* xw = scratch + warp * 1024; // 4 nodes x 256 staging

    // ---- phase 0: weights (input-side) + tree metadata -> smem -----------
    {
        const int jb2 = g * 32;
        for (int it = 0; it < 16; it++) {
            int k = it * 16 + (tid >> 5);
            int col = tid & 31;
            int didx = (k >> 2) * 128 + col * 4 + (k & 3);
            int sidx = k * Hv + jb2 + col;
            Wi4[didx] = W_ix[sidx];
            Wo4[didx] = W_ox[sidx];
            Wu4[didx] = W_ux[sidx];
            Wf4[didx] = W_fx[sidx];
        }
        if (tid < 32) sm_tloff[tid] = g_tl_off[b * 32 + tid] - b * 128;
        if (tid >= 32 && tid < 160) sm_tln[tid - 32] = g_tl_nodes[b * 128 + (tid - 32)];
        int cbase = g_coff[b * 128];
        int cend  = g_coff[b * 128 + 128];
        if (tid >= 160 && tid < 289) sm_coff[tid - 160] = g_coff[b * 128 + (tid - 160)] - cbase;
        for (int i = tid; i < cend - cbase; i += NTHR) sm_child[i] = g_children[cbase + i];
    }
    const float bi = b_ix[J] + b_ih[J];
    const float bf = b_fx[J] + b_fh[J];
    __syncthreads();

    // ---- P1: 4 projections, 4 nodes/warp-iter; leaves finished inline ----
    {
        for (int t = 0; t < 2; t++) {
            int nb = b * Sv + (warp + t * 16) * 4;   // 4 contiguous nodes
            int hgt0 = nheight[nb + 0], hgt1 = nheight[nb + 1];
            int hgt2 = nheight[nb + 2], hgt3 = nheight[nb + 3];
            __syncwarp();
            #pragma unroll
            for (int mm = 0; mm < 4; mm++) {
                int n = nb + mm;
                const float4* er = (const float4*)(emb_W + (size_t)xs[n] * DEv);
                const float4* rr = (const float4*)(rel_W + (size_t)rels[n] * DRv);
                float4 a = er[lane];
                float4 bb = (lane < 16) ? er[lane + 32] : rr[lane - 16];
                float4* dm = (float4*)(xw + mm * 256);
                dm[lane] = a; dm[lane + 32] = bb;
            }
            __syncwarp();
            unsigned long long acc[16];
            #pragma unroll
            for (int q = 0; q < 16; q++) acc[q] = 0ull;
            #pragma unroll 4
            for (int k4 = 0; k4 < 64; k4++) {
                ulonglong2 wi = *(const ulonglong2*)&Wi4[k4 * 128 + lane * 4];
                ulonglong2 wf = *(const ulonglong2*)&Wf4[k4 * 128 + lane * 4];
                ulonglong2 wo = *(const ulonglong2*)&Wo4[k4 * 128 + lane * 4];
                ulonglong2 wu = *(const ulonglong2*)&Wu4[k4 * 128 + lane * 4];
                #pragma unroll
                for (int mm = 0; mm < 4; mm++) {
                    ulonglong2 xv = *(const ulonglong2*)&xw[mm * 256 + k4 * 4];
                    FFMA2(acc[mm * 4 + 0], xv.x, wi.x); FFMA2(acc[mm * 4 + 0], xv.y, wi.y);
                    FFMA2(acc[mm * 4 + 1], xv.x, wf.x); FFMA2(acc[mm * 4 + 1], xv.y, wf.y);
                    FFMA2(acc[mm * 4 + 2], xv.x, wo.x); FFMA2(acc[mm * 4 + 2], xv.y, wo.y);
                    FFMA2(acc[mm * 4 + 3], xv.x, wu.x); FFMA2(acc[mm * 4 + 3], xv.y, wu.y);
                }
            }
            #pragma unroll
            for (int mm = 0; mm < 4; mm++) {
                int hgt = (mm == 0) ? hgt0 : (mm == 1) ? hgt1 : (mm == 2) ? hgt2 : hgt3;
                size_t nx = (size_t)(nb + mm) * Hv + J;
                float vi = pairsum(acc[mm * 4 + 0]) + bi;
                float vf = pairsum(acc[mm * 4 + 1]) + bf;
                float vo = pairsum(acc[mm * 4 + 2]);
                float vu = pairsum(acc[mm * 4 + 3]);
                if (hgt == 0) {
                    float iv = sigf(vi);
                    float ov = sigf(vo);
                    float uv = __tanhf(vu);
                    float cv = iv * uv;
                    g_c[nx] = cv;
                    g_h[nx] = ov * __tanhf(cv);
                } else {
                    g_proj[0][nx] = vi;
                    g_proj[1][nx] = vf;
                    g_proj[2][nx] = vo;
                    g_proj[3][nx] = vu;
                }
            }
        }
    }
    __syncthreads();
    // publish level 0 immediately (peers can start level 1 while we reload)
    if (tid == 0) st_rel(&g_lflag[(b * NLEVF + 0) * 8 + g], 1u);

    // ---- reload RECURRENT weight col-slices ------------------------------
    {
        const int jb2 = g * 32;
        for (int it = 0; it < 16; it++) {
            int k = it * 16 + (tid >> 5);
            int col = tid & 31;
            int didx = (k >> 2) * 128 + col * 4 + (k & 3);
            int sidx = k * Hv + jb2 + col;
            Wi4[didx] = W_ih[sidx];
            Wo4[didx] = W_oh[sidx];
            Wu4[didx] = W_uh[sidx];
            Wf4[didx] = W_fh[sidx];
        }
    }
    __syncthreads();

    // ---- bottom-up levels: adaptive batch, one flag per level ------------
    {
        const int tmax = g_tmax[b];
        for (int lev = 1; lev <= tmax; lev++) {
            // one-hop wait: all 8 CTAs of my tree published level lev-1
            if (warp == 0) {
                unsigned* fp = &g_lflag[(b * NLEVF + lev - 1) * 8 + (lane & 7)];
                for (;;) {
                    unsigned d = (lane < 8) ? ld_cg(fp) : 1u;
                    if (__all_sync(0xFFFFFFFFu, d != 0u)) break;
                }
            }
            __syncthreads();

            // (a) fh-phase: fh = W_fh . h for nodes of height lev-1
            {
                int pb = sm_tloff[lev - 1], pe = sm_tloff[lev];
                int pc = pe - pb;
                int cw = (pc + 15) >> 4; if (cw > 4) cw = 4; if (cw < 1) cw = 1;
                for (int i0 = pb + warp * cw; i0 < pe; i0 += 16 * cw) {
                    int mc = pe - i0; if (mc > cw) mc = cw;
                    if (mc == 1) {
                        int n = sm_tln[i0];
                        const float4* hsrc = (const float4*)(g_h + (size_t)n * Hv);
                        __syncwarp();
                        ((float4*)xw)[lane] = hsrc[lane];
                        ((float4*)xw)[lane + 32] = hsrc[lane + 32];
                        __syncwarp();
                        unsigned long long aX = 0, aY = 0;
                        #pragma unroll 8
                        for (int k4 = 0; k4 < 64; k4++) {
                            ulonglong2 wf = *(const ulonglong2*)&Wf4[k4 * 128 + lane * 4];
                            ulonglong2 xv = *(const ulonglong2*)&xw[k4 * 4];
                            FFMA2(aX, xv.x, wf.x); FFMA2(aY, xv.y, wf.y);
                        }
                        g_fh[(size_t)n * Hv + J] = pairsum(aX) + pairsum(aY);
                    } else {
                        int nid[4];
                        __syncwarp();
                        #pragma unroll
                        for (int mm = 0; mm < 4; mm++) {
                            if (mm < mc) {
                                int n = sm_tln[i0 + mm];
                                nid[mm] = n;
                                const float4* hsrc = (const float4*)(g_h + (size_t)n * Hv);
                                float4* dm = (float4*)(xw + mm * 256);
                                dm[lane] = hsrc[lane];
                                dm[lane + 32] = hsrc[lane + 32];
                            } else nid[mm] = -1;
                        }
                        __syncwarp();
                        unsigned long long af[4] = {0, 0, 0, 0};
                        #pragma unroll 4
                        for (int k4 = 0; k4 < 64; k4++) {
                            ulonglong2 wf = *(const ulonglong2*)&Wf4[k4 * 128 + lane * 4];
                            #pragma unroll
                            for (int mm = 0; mm < 4; mm++) {
                                ulonglong2 xv = *(const ulonglong2*)&xw[mm * 256 + k4 * 4];
                                FFMA2(af[mm], xv.x, wf.x); FFMA2(af[mm], xv.y, wf.y);
                            }
                        }
                        #pragma unroll
                        for (int mm = 0; mm < 4; mm++)
                            if (nid[mm] >= 0)
                                g_fh[(size_t)nid[mm] * Hv + J] = pairsum(af[mm]);
                    }
                }
            }
            __syncthreads();

            // (b) gate-phase: nodes of height lev, adaptive batch
            {
                int base = sm_tloff[lev], lend = sm_tloff[lev + 1];
                int cnt = lend - base;
                int cw = (cnt + 15) >> 4; if (cw > 4) cw = 4; if (cw < 1) cw = 1;
                for (int i0 = base + warp * cw; i0 < lend; i0 += 16 * cw) {
                    int mc = lend - i0; if (mc > cw) mc = cw;
                    if (mc == 1) {
                        int n = sm_tln[i0];
                        int nloc = n - b * Sv;
                        float fx = g_proj[1][(size_t)n * Hv + J];
                        int cs = sm_coff[nloc], ce = sm_coff[nloc + 1];
                        float4 s0 = make_float4(0, 0, 0, 0), s1 = make_float4(0, 0, 0, 0);
                        float fc = 0.0f;
                        for (int ci = cs; ci < ce; ci++) {
                            int ch = sm_child[ci];
                            const float4* hsrc = (const float4*)(g_h + (size_t)ch * Hv);
                            float4 v0 = hsrc[lane], v1 = hsrc[lane + 32];
                            s0.x += v0.x; s0.y += v0.y; s0.z += v0.z; s0.w += v0.w;
                            s1.x += v1.x; s1.y += v1.y; s1.z += v1.z; s1.w += v1.w;
                            fc += sigf(g_fh[(size_t)ch * Hv + J] + fx)
                                  * g_c[(size_t)ch * Hv + J];
                        }
                        __syncwarp();
                        ((float4*)xw)[lane] = s0; ((float4*)xw)[lane + 32] = s1;
                        __syncwarp();
                        unsigned long long ai = 0, aj = 0, ao = 0, ap = 0, au = 0, av = 0;
                        #pragma unroll 4
                        for (int k4 = 0; k4 < 64; k4++) {
                            ulonglong2 xv = *(const ulonglong2*)&xw[k4 * 4];
                            ulonglong2 wi = *(const ulonglong2*)&Wi4[k4 * 128 + lane * 4];
                            ulonglong2 wo = *(const ulonglong2*)&Wo4[k4 * 128 + lane * 4];
                            ulonglong2 wu = *(const ulonglong2*)&Wu4[k4 * 128 + lane * 4];
                            FFMA2(ai, xv.x, wi.x); FFMA2(aj, xv.y, wi.y);
                            FFMA2(ao, xv.x, wo.x); FFMA2(ap, xv.y, wo.y);
                            FFMA2(au, xv.x, wu.x); FFMA2(av, xv.y, wu.y);
                        }
                        size_t nx = (size_t)n * Hv + J;
                        float iv = sigf(g_proj[0][nx] + pairsum(ai) + pairsum(aj));
                        float ov = sigf(g_proj[2][nx] + pairsum(ao) + pairsum(ap));
                        float uv = __tanhf(g_proj[3][nx] + pairsum(au) + pairsum(av));
                        float cn = iv * uv + fc;
                        g_c[nx] = cn;
                        g_h[nx] = ov * __tanhf(cn);
                    } else {
                        int nid[4]; float fcv[4];
                        __syncwarp();
                        #pragma unroll
                        for (int mm = 0; mm < 4; mm++) {
                            fcv[mm] = 0.0f;
                            if (mm < mc) {
                                int n = sm_tln[i0 + mm];
                                nid[mm] = n;
                                int nloc = n - b * Sv;
                                float fx = g_proj[1][(size_t)n * Hv + J];
                                int cs = sm_coff[nloc], ce = sm_coff[nloc + 1];
                                float4 s0 = make_float4(0, 0, 0, 0);
                                float4 s1 = make_float4(0, 0, 0, 0);
                                float fc = 0.0f;
                                for (int ci = cs; ci < ce; ci++) {
                                    int ch = sm_child[ci];
                                    const float4* hsrc = (const float4*)(g_h + (size_t)ch * Hv);
                                    float4 v0 = hsrc[lane], v1 = hsrc[lane + 32];
                                    s0.x += v0.x; s0.y += v0.y; s0.z += v0.z; s0.w += v0.w;
                                    s1.x += v1.x; s1.y += v1.y; s1.z += v1.z; s1.w += v1.w;
                                    fc += sigf(g_fh[(size_t)ch * Hv + J] + fx)
                                          * g_c[(size_t)ch * Hv + J];
                                }
                                float4* dm = (float4*)(xw + mm * 256);
                                dm[lane] = s0; dm[lane + 32] = s1;
                                fcv[mm] = fc;
                            } else nid[mm] = -1;
                        }
                        __syncwarp();
                        unsigned long long ai[4] = {0, 0, 0, 0};
                        unsigned long long ao[4] = {0, 0, 0, 0};
                        unsigned long long au[4] = {0, 0, 0, 0};
                        #pragma unroll 2
                        for (int k4 = 0; k4 < 64; k4++) {
                            ulonglong2 wi = *(const ulonglong2*)&Wi4[k4 * 128 + lane * 4];
                            ulonglong2 wo = *(const ulonglong2*)&Wo4[k4 * 128 + lane * 4];
                            ulonglong2 wu = *(const ulonglong2*)&Wu4[k4 * 128 + lane * 4];
                            #pragma unroll
                            for (int mm = 0; mm < 4; mm++) {
                                ulonglong2 xv = *(const ulonglong2*)&xw[mm * 256 + k4 * 4];
                                FFMA2(ai[mm], xv.x, wi.x); FFMA2(ai[mm], xv.y, wi.y);
                                FFMA2(ao[mm], xv.x, wo.x); FFMA2(ao[mm], xv.y, wo.y);
                                FFMA2(au[mm], xv.x, wu.x); FFMA2(au[mm], xv.y, wu.y);
                            }
                        }
                        #pragma unroll
                        for (int mm = 0; mm < 4; mm++) {
                            if (nid[mm] < 0) continue;
                            size_t nx = (size_t)nid[mm] * Hv + J;
                            float iv = sigf(g_proj[0][nx] + pairsum(ai[mm]));
                            float ov = sigf(g_proj[2][nx] + pairsum(ao[mm]));
                            float uv = __tanhf(g_proj[3][nx] + pairsum(au[mm]));
                            float cn = iv * uv + fcv[mm];
                            g_c[nx] = cn;
                            g_h[nx] = ov * __tanhf(cn);
                        }
                    }
                }
            }
            __syncthreads();
            if (tid == 0) st_rel(&g_lflag[(b * NLEVF + lev) * 8 + g], 1u);
        }
    }

    // ---- pooling (column-local) + head -----------------------------------
    __syncthreads();
    {
        float m = -1e30f;
        for (int s2 = warp; s2 < Sv; s2 += 16)
            m = fmaxf(m, g_h[(size_t)(b * Sv + s2) * Hv + J]);
        scratch[warp * 32 + lane] = m;
        __syncthreads();
        if (tid < 32) {
            float mm = scratch[tid];
            #pragma unroll
            for (int r = 1; r < 16; r++) mm = fmaxf(mm, scratch[r * 32 + tid]);
            g_pooled[b * Hv + g * 32 + tid] = mm;
        }
        __syncthreads();
        if (tid == 0) red_add_rel(&g_pdone[b * 32], 1u);
    }
    if (g == 0) {
        if (tid == 0) { while (ld_cg(&g_pdone[b * 32]) < 8u) { } }
        __syncthreads();
        if (warp < Lv) {
            float acc = 0.0f;
            for (int k = lane; k < Hv; k += 32)
                acc += g_pooled[b * Hv + k] * W_out[k * Lv + warp];
            #pragma unroll
            for (int off = 16; off; off >>= 1)
                acc += __shfl_down_sync(0xFFFFFFFFu, acc, off);
            if (lane == 0) out[b * Lv + warp] = acc + b_out[warp];
        }
    }
}

// ---------------- launch --------------------------------------------------
extern "C" void kernel_launch(void* const* d_in, const int* in_sizes, int n_in,
                              void* d_out, int out_size) {
    const int s = (n_in >= 22) ? 1 : 0;   // robust to n_levels scalar presence
    const int* xs          = (const int*)d_in[0];
    const int* rels        = (const int*)d_in[1];
    const int* child_idx   = (const int*)d_in[2];
    const int* parent_idx  = (const int*)d_in[3];
    const int* node_height = (const int*)d_in[4];
    const float* emb_W = (const float*)d_in[5 + s];
    const float* rel_W = (const float*)d_in[6 + s];
    const float* W_ix  = (const float*)d_in[7 + s];
    const float* b_ix  = (const float*)d_in[8 + s];
    const float* W_ih  = (const float*)d_in[9 + s];
    const float* b_ih  = (const float*)d_in[10 + s];
    const float* W_fx  = (const float*)d_in[11 + s];
    const float* b_fx  = (const float*)d_in[12 + s];
    const float* W_fh  = (const float*)d_in[13 + s];
    const float* b_fh  = (const float*)d_in[14 + s];
    const float* W_ox  = (const float*)d_in[15 + s];
    const float* W_oh  = (const float*)d_in[16 + s];
    const float* W_ux  = (const float*)d_in[17 + s];
    const float* W_uh  = (const float*)d_in[18 + s];
    const float* W_out = (const float*)d_in[19 + s];
    const float* b_out = (const float*)d_in[20 + s];
    float* out = (float*)d_out;

    cudaFuncSetAttribute(main_kernel, cudaFuncAttributeMaxDynamicSharedMemorySize, SMEM_BYTES);

    setup_kernel<<<Bv, 128>>>(child_idx, parent_idx, node_height);
    main_kernel<<<NCTA, NTHR, SMEM_BYTES>>>(xs, rels, node_height, emb_W, rel_W,
                                            W_ix, b_ix, W_ih, b_ih,
                                            W_fx, b_fx, W_fh, b_fh,
                                            W_ox, W_oh, W_ux, W_uh,
                                            W_out, b_out, out);
}